// round 6
// baseline (speedup 1.0000x reference)
#include <cuda_runtime.h>
#include <cstdint>

// ---------------- problem constants ----------------
#define B_TOT   4096
#define K1      30
#define K2      80
#define NT      7
#define NTILE   49          // 7*7
#define TPI     1470        // K1*NTILE tiles per image
#define C2N     1280        // K2*16
#define ETA_PER_B 13230     // TPI*9

// output layout: x_rec | mean | log_var | eta  (flat f32, tuple order)
#define OUT_XREC 0ull
#define OUT_MEAN 3211264ull
#define OUT_LV   8454144ull
#define OUT_ETA  13697024ull

// ---------------- scratch (device globals; no runtime alloc) ----------------
__device__ float         g_pooled[B_TOT * TPI];
__device__ unsigned char g_zeta2 [B_TOT * TPI];
__device__ float         g_s     [B_TOT * C2N];
__device__ float         g_s2    [B_TOT * TPI];

// ---------------- threefry2x32 (JAX-exact) ----------------
__host__ __device__ inline void tf2x32(uint32_t k0, uint32_t k1,
                                       uint32_t x0, uint32_t x1,
                                       uint32_t& o0, uint32_t& o1) {
    uint32_t ks2 = k0 ^ k1 ^ 0x1BD11BDAu;
    x0 += k0; x1 += k1;
#define TF_RND(r) { x0 += x1; x1 = (x1 << (r)) | (x1 >> (32 - (r))); x1 ^= x0; }
    TF_RND(13) TF_RND(15) TF_RND(26) TF_RND(6)
    x0 += k1;  x1 += ks2 + 1u;
    TF_RND(17) TF_RND(29) TF_RND(16) TF_RND(24)
    x0 += ks2; x1 += k0 + 2u;
    TF_RND(13) TF_RND(15) TF_RND(26) TF_RND(6)
    x0 += k0;  x1 += k1 + 3u;
    TF_RND(17) TF_RND(29) TF_RND(16) TF_RND(24)
    x0 += k1;  x1 += ks2 + 4u;
    TF_RND(13) TF_RND(15) TF_RND(26) TF_RND(6)
    x0 += ks2; x1 += k0 + 5u;
#undef TF_RND
    o0 = x0; o1 = x1;
}

// partitionable-mode 32-bit random bits: counter = 64-bit index (hi=0 here),
// output = xor of the two threefry outputs.
__device__ __forceinline__ uint32_t tf_bits(uint32_t k0, uint32_t k1, uint32_t idx) {
    uint32_t a, b;
    tf2x32(k0, k1, 0u, idx, a, b);
    return a ^ b;
}

__device__ __forceinline__ float bits_to_f01(uint32_t b) {
    return __uint_as_float((b >> 9) | 0x3F800000u) - 1.0f;   // [0,1)
}
__device__ __forceinline__ float gumbelf(uint32_t b) {
    const float TINY = 1.17549435e-38f;
    float f = bits_to_f01(b);
    float u = f + TINY;              // f*(1-tiny)+tiny == f+tiny in f32
    u = fmaxf(TINY, u);
    return -logf(-logf(u));
}
__device__ __forceinline__ float normalf(uint32_t b) {
    const float LO = -0.99999994f;   // nextafter(-1, 0)
    float f = bits_to_f01(b);
    float u = fmaf(f, 2.0f, LO);     // (hi-lo) rounds to exactly 2.0f; f*2 exact
    u = fmaxf(LO, u);
    return 1.41421356237f * erfinvf(u);
}

// ---------------- kernel 1: enc1 conv + pool MLP + eta + categorical x2 ----------------
__device__ __forceinline__ void pool_mlp(const float t[9],
                                         const float* __restrict__ w1s,
                                         const float* __restrict__ w2s,
                                         float* __restrict__ eta_out,  // gmem
                                         float l[9]) {
    float h1[9];
#pragma unroll
    for (int o = 0; o < 9; o++) {
        float a = 0.f;
#pragma unroll
        for (int tt = 0; tt < 9; tt++) a += t[tt] * w1s[o * 9 + tt];
        h1[o] = tanhf(a);
    }
    float lg[9]; float mx = -3.402823466e38f;
#pragma unroll
    for (int o = 0; o < 9; o++) {
        float a = 0.f;
#pragma unroll
        for (int tt = 0; tt < 9; tt++) a += h1[tt] * w2s[o * 9 + tt];
        lg[o] = a; mx = fmaxf(mx, a);
    }
    float s = 0.f;
#pragma unroll
    for (int o = 0; o < 9; o++) { lg[o] = expf(lg[o] - mx); s += lg[o]; }
    float inv = 1.0f / s;
#pragma unroll
    for (int o = 0; o < 9; o++) {
        float e = lg[o] * inv;
        eta_out[o] = e;
        l[o] = logf(e);
    }
}

__global__ __launch_bounds__(256) void k_enc_pool(
    const float* __restrict__ x, const float* __restrict__ enc1_w,
    const float* __restrict__ pw1, const float* __restrict__ pw2,
    float* __restrict__ out,
    uint32_t kp0, uint32_t kp1, uint32_t ku0, uint32_t ku1)
{
    __shared__ float xs[784], ws[K1 * 64], w1s[81], w2s[81];
    int b = blockIdx.x;             // one image per block
    int tid = threadIdx.x;
    for (int i = tid; i < 784; i += 256) xs[i] = x[(size_t)b * 784 + i];
    for (int i = tid; i < K1 * 64; i += 256) ws[i] = enc1_w[i];
    if (tid < 81) { w1s[tid] = pw1[tid]; w2s[tid] = pw2[tid]; }
    __syncthreads();

    for (int w = tid; w < TPI; w += 256) {
        int c = w / NTILE, nm = w % NTILE;
        int n = nm / NT, m = nm % NT;
        int y0 = 3 * n, x0 = 3 * m;
        const float* wc = &ws[c * 64];

        float t[9];
#pragma unroll
        for (int tt = 0; tt < 9; tt++) {
            int py = y0 + tt / 3, px = x0 + tt % 3;
            float a = 0.f;
#pragma unroll
            for (int u = 0; u < 8; u++) {
#pragma unroll
                for (int v = 0; v < 8; v++)
                    a += xs[(py + u) * 28 + px + v] * wc[u * 8 + v];
            }
            t[tt] = a;
        }

        float l[9];
        pool_mlp(t, w1s, w2s, &out[OUT_ETA + (size_t)b * ETA_PER_B + (size_t)w * 9], l);

        // gumbel-max categorical: pool key -> pooled value, unpool key -> zeta2 idx
        uint32_t e0 = (uint32_t)b * (uint32_t)ETA_PER_B + (uint32_t)w * 9u;
        float best = -3.4e38f, best2 = -3.4e38f;
        float pv = 0.f;
        int z2 = 0;
#pragma unroll
        for (int tt = 0; tt < 9; tt++) {
            float sp = gumbelf(tf_bits(kp0, kp1, e0 + tt)) + l[tt];
            if (sp > best) { best = sp; pv = t[tt]; }
            float su = gumbelf(tf_bits(ku0, ku1, e0 + tt)) + l[tt];
            if (su > best2) { best2 = su; z2 = tt; }
        }
        g_pooled[(size_t)b * TPI + w] = pv;
        g_zeta2[(size_t)b * TPI + w] = (unsigned char)z2;
    }
}

// ---------------- kernel 2: conv2 + per-channel MLPs + reparam sample ----------------
__global__ __launch_bounds__(256) void k_enc2_code(
    const float* __restrict__ enc2_w,
    const float* __restrict__ h_w,  const float* __restrict__ h_b,
    const float* __restrict__ mean_w, const float* __restrict__ mean_b,
    const float* __restrict__ lv_w,   const float* __restrict__ lv_b,
    float* __restrict__ out, uint32_t kc0, uint32_t kc1)
{
    __shared__ float pl[TPI];
    __shared__ float flat[C2N];
    __shared__ float hsm[C2N];
    int b = blockIdx.x, tid = threadIdx.x;

    for (int i = tid; i < TPI; i += 256) pl[i] = g_pooled[(size_t)b * TPI + i];
    __syncthreads();

    // conv2 -> flat [k2*16 + i*4+j]
    for (int r = tid; r < C2N; r += 256) {
        int k = r / 16, ij = r % 16, ii = ij / 4, jj = ij % 4;
        float a = 0.f;
        for (int c = 0; c < K1; c++) {
            const float* pc = &pl[c * NTILE + ii * NT + jj];
            const float* wc = &enc2_w[k * (K1 * 16) + c * 16];
#pragma unroll
            for (int u = 0; u < 4; u++)
#pragma unroll
                for (int v = 0; v < 4; v++)
                    a += pc[u * NT + v] * wc[u * 4 + v];
        }
        flat[r] = a;
    }
    __syncthreads();

    // h = tanh(flat @ h_w^T + h_b)
    for (int r = tid; r < C2N; r += 256) {
        int k = r / 16;
        const float* wr = &h_w[r * 16];
        const float* fr = &flat[k * 16];
        float a = h_b[r];
#pragma unroll
        for (int i2 = 0; i2 < 16; i2++) a += fr[i2] * wr[i2];
        hsm[r] = tanhf(a);
    }
    __syncthreads();

    // mean / logvar, then reparameterized normal sample
    for (int r = tid; r < C2N; r += 256) {
        int k = r / 16;
        const float* wm = &mean_w[r * 16];
        const float* wl = &lv_w[r * 16];
        const float* h0 = &hsm[k * 16];
        float m0 = mean_b[r], l0 = lv_b[r];
#pragma unroll
        for (int i2 = 0; i2 < 16; i2++) {
            float a = h0[i2];
            m0 += a * wm[i2];  l0 += a * wl[i2];
        }
        out[OUT_MEAN + (size_t)b * C2N + r] = m0;
        out[OUT_LV   + (size_t)b * C2N + r] = l0;

        uint32_t e = (uint32_t)b * (uint32_t)C2N + (uint32_t)r;
        g_s[(size_t)b * C2N + r] = m0 + expf(0.5f * l0) * normalf(tf_bits(kc0, kc1, e));
    }
}

// ---------------- kernel 3: dec2 transposed conv ----------------
__global__ __launch_bounds__(256) void k_dec2(const float* __restrict__ dec2_w)
{
    __shared__ float ss[C2N];
    int b = blockIdx.x, tid = threadIdx.x;
    for (int i = tid; i < C2N; i += 256) ss[i] = g_s[(size_t)b * C2N + i];
    __syncthreads();

    for (int o = tid; o < TPI; o += 256) {
        int c1 = o / NTILE, yx = o % NTILE, y = yx / NT, xx = yx % NT;
        int ilo = max(0, y - 3),  ihi = min(3, y);
        int jlo = max(0, xx - 3), jhi = min(3, xx);
        float a = 0.f;
        for (int c2 = 0; c2 < K2; c2++) {
            const float* sc = &ss[c2 * 16];
            const float* wc = &dec2_w[c2 * (K1 * 16) + c1 * 16];
            for (int i = ilo; i <= ihi; i++) {
                int u = y - i;
                for (int j = jlo; j <= jhi; j++) {
                    int v = xx - j;
                    a += sc[i * 4 + j] * wc[u * 4 + v];
                }
            }
        }
        g_s2[(size_t)b * TPI + o] = a;
    }
}

// ---------------- kernel 4: unpool + dec1 transposed conv + diag noise ----------------
__global__ __launch_bounds__(256) void k_dec1(
    const float* __restrict__ dec1_w, const float* __restrict__ alpha_p,
    float* __restrict__ out, uint32_t kn0, uint32_t kn1)
{
    __shared__ float s2s[TPI];
    __shared__ int   z2s[TPI];
    __shared__ float ws[K1 * 64];
    int b = blockIdx.x, tid = threadIdx.x;
    for (int i = tid; i < TPI; i += 256) {
        s2s[i] = g_s2[(size_t)b * TPI + i];
        z2s[i] = (int)g_zeta2[(size_t)b * TPI + i];
    }
    for (int i = tid; i < K1 * 64; i += 256) ws[i] = dec1_w[i];
    __syncthreads();

    float inv_alpha = 1.0f / alpha_p[0];

    for (int p = tid; p < 784; p += 256) {
        int y = p / 28, xx = p % 28;
        int nlo = (y  >= 9) ? (y  - 7) / 3 : 0;
        int nhi = min(6, y / 3);
        int mlo = (xx >= 9) ? (xx - 7) / 3 : 0;
        int mhi = min(6, xx / 3);
        float a = 0.f;
        for (int c = 0; c < K1; c++) {
            int cb = c * NTILE;
            const float* wc = &ws[c * 64];
            for (int n = nlo; n <= nhi; n++) {
                int i3 = 3 * n;
                for (int m = mlo; m <= mhi; m++) {
                    int idx = cb + n * NT + m;
                    int z = z2s[idx];
                    int u = y - i3 - z / 3;
                    int v = xx - 3 * m - z % 3;
                    if ((unsigned)u < 8u && (unsigned)v < 8u)
                        a += s2s[idx] * wc[u * 8 + v];
                }
            }
        }
        if (y == xx) {
            uint32_t e = (uint32_t)b * 784u + (uint32_t)y * 29u;
            a += inv_alpha * normalf(tf_bits(kn0, kn1, e));
        }
        out[OUT_XREC + (size_t)b * 784 + p] = a;
    }
}

// ---------------- launch ----------------
extern "C" void kernel_launch(void* const* d_in, const int* in_sizes, int n_in,
                              void* d_out, int out_size) {
    (void)in_sizes; (void)n_in; (void)out_size;
    const float* x      = (const float*)d_in[0];
    const float* enc1_w = (const float*)d_in[1];
    const float* pw1    = (const float*)d_in[2];
    const float* pw2    = (const float*)d_in[3];
    const float* enc2_w = (const float*)d_in[4];
    const float* h_w    = (const float*)d_in[5];
    const float* h_b    = (const float*)d_in[6];
    const float* mean_w = (const float*)d_in[7];
    const float* mean_b = (const float*)d_in[8];
    const float* lv_w   = (const float*)d_in[9];
    const float* lv_b   = (const float*)d_in[10];
    const float* dec2_w = (const float*)d_in[11];
    const float* dec1_w = (const float*)d_in[12];
    const float* alpha  = (const float*)d_in[13];
    float* out = (float*)d_out;

    // jax.random.key(42) = (0,42).
    // Partitionable (fold-like) split: key_j = threefry2x32(key, (0, j)).
    uint32_t kp0, kp1, ku0, ku1, kc0, kc1, kn0, kn1;
    tf2x32(0u, 42u, 0u, 0u, kp0, kp1);   // k_pool
    tf2x32(0u, 42u, 0u, 1u, ku0, ku1);   // k_unpool
    tf2x32(0u, 42u, 0u, 2u, kc0, kc1);   // k_code
    tf2x32(0u, 42u, 0u, 3u, kn0, kn1);   // k_noise

    k_enc_pool<<<B_TOT, 256>>>(x, enc1_w, pw1, pw2, out, kp0, kp1, ku0, ku1);
    k_enc2_code<<<B_TOT, 256>>>(enc2_w, h_w, h_b, mean_w, mean_b, lv_w, lv_b,
                                out, kc0, kc1);
    k_dec2<<<B_TOT, 256>>>(dec2_w);
    k_dec1<<<B_TOT, 256>>>(dec1_w, alpha, out, kn0, kn1);
}

// round 7
// speedup vs baseline: 2.4037x; 2.4037x over previous
#include <cuda_runtime.h>
#include <cstdint>

// ---------------- problem constants ----------------
#define B_TOT   4096
#define K1      30
#define K2      80
#define NT      7
#define NTILE   49          // 7*7
#define TPI     1470        // K1*NTILE tiles per image
#define C2N     1280        // K2*16
#define ETA_PER_B 13230     // TPI*9

// output layout: x_rec | mean | log_var | eta  (flat f32, tuple order)
#define OUT_XREC 0ull
#define OUT_MEAN 3211264ull
#define OUT_LV   8454144ull
#define OUT_ETA  13697024ull

// ---------------- threefry2x32 (JAX-exact) ----------------
#ifdef __CUDA_ARCH__
#define TF_ROT(x, r) __funnelshift_l((x), (x), (r))
#else
#define TF_ROT(x, r) (((x) << (r)) | ((x) >> (32 - (r))))
#endif

__host__ __device__ inline void tf2x32(uint32_t k0, uint32_t k1,
                                       uint32_t x0, uint32_t x1,
                                       uint32_t& o0, uint32_t& o1) {
    uint32_t ks2 = k0 ^ k1 ^ 0x1BD11BDAu;
    x0 += k0; x1 += k1;
#define TF_RND(r) { x0 += x1; x1 = TF_ROT(x1, r); x1 ^= x0; }
    TF_RND(13) TF_RND(15) TF_RND(26) TF_RND(6)
    x0 += k1;  x1 += ks2 + 1u;
    TF_RND(17) TF_RND(29) TF_RND(16) TF_RND(24)
    x0 += ks2; x1 += k0 + 2u;
    TF_RND(13) TF_RND(15) TF_RND(26) TF_RND(6)
    x0 += k0;  x1 += k1 + 3u;
    TF_RND(17) TF_RND(29) TF_RND(16) TF_RND(24)
    x0 += k1;  x1 += ks2 + 4u;
    TF_RND(13) TF_RND(15) TF_RND(26) TF_RND(6)
    x0 += ks2; x1 += k0 + 5u;
#undef TF_RND
    o0 = x0; o1 = x1;
}

// partitionable-mode 32-bit bits: counter = 64-bit idx (hi=0), out = o0 ^ o1.
__device__ __forceinline__ uint32_t tf_bits(uint32_t k0, uint32_t k1, uint32_t idx) {
    uint32_t a, b;
    tf2x32(k0, k1, 0u, idx, a, b);
    return a ^ b;
}

__device__ __forceinline__ float bits_to_f01(uint32_t b) {
    return __uint_as_float((b >> 9) | 0x3F800000u) - 1.0f;   // [0,1)
}
__device__ __forceinline__ float gumbelf(uint32_t b) {
    const float TINY = 1.17549435e-38f;
    float f = bits_to_f01(b);
    float u = f + TINY;
    u = fmaxf(TINY, u);
    return -logf(-logf(u));
}
__device__ __forceinline__ float normalf(uint32_t b) {
    const float LO = -0.99999994f;   // nextafter(-1, 0)
    float f = bits_to_f01(b);
    float u = fmaf(f, 2.0f, LO);     // (hi-lo) rounds to exactly 2.0f; f*2 exact
    u = fmaxf(LO, u);
    return 1.41421356237f * erfinvf(u);
}

// ---------------- pool MLP (bit-identical to round 6) ----------------
__device__ __forceinline__ void pool_mlp(const float t[9],
                                         const float* __restrict__ w1s,
                                         const float* __restrict__ w2s,
                                         float* __restrict__ eta_out,  // gmem
                                         float l[9]) {
    float h1[9];
#pragma unroll
    for (int o = 0; o < 9; o++) {
        float a = 0.f;
#pragma unroll
        for (int tt = 0; tt < 9; tt++) a += t[tt] * w1s[o * 9 + tt];
        h1[o] = tanhf(a);
    }
    float lg[9]; float mx = -3.402823466e38f;
#pragma unroll
    for (int o = 0; o < 9; o++) {
        float a = 0.f;
#pragma unroll
        for (int tt = 0; tt < 9; tt++) a += h1[tt] * w2s[o * 9 + tt];
        lg[o] = a; mx = fmaxf(mx, a);
    }
    float s = 0.f;
#pragma unroll
    for (int o = 0; o < 9; o++) { lg[o] = expf(lg[o] - mx); s += lg[o]; }
    float inv = 1.0f / s;
#pragma unroll
    for (int o = 0; o < 9; o++) {
        float e = lg[o] * inv;
        eta_out[o] = e;
        l[o] = logf(e);
    }
}

// ---------------- ONE fused kernel: whole pipeline per image ----------------
__global__ __launch_bounds__(256) void k_fused(
    const float* __restrict__ x,
    const float* __restrict__ enc1_w,
    const float* __restrict__ pw1, const float* __restrict__ pw2,
    const float* __restrict__ enc2_w,
    const float* __restrict__ h_w,  const float* __restrict__ h_b,
    const float* __restrict__ mean_w, const float* __restrict__ mean_b,
    const float* __restrict__ lv_w,   const float* __restrict__ lv_b,
    const float* __restrict__ dec2_w, const float* __restrict__ dec1_w,
    const float* __restrict__ alpha_p,
    float* __restrict__ out,
    uint32_t kp0, uint32_t kp1, uint32_t ku0, uint32_t ku1,
    uint32_t kc0, uint32_t kc1, uint32_t kn0, uint32_t kn1)
{
    __shared__ float xs[784];
    __shared__ float ws[K1 * 64];      // enc1_w during stage 1, dec1_w during stage 4
    __shared__ float w1s[81], w2s[81];
    __shared__ float pooled[TPI];      // stage-1 output, reused as s2 after stage 3
    __shared__ float flat[C2N];        // conv2 output, reused as s after stage 2c
    __shared__ float hsm[C2N];
    __shared__ unsigned char zs[TPI];  // packed (zy<<2)|zx

    int b = blockIdx.x, tid = threadIdx.x;

    for (int i = tid; i < 784; i += 256) xs[i] = x[(size_t)b * 784 + i];
    for (int i = tid; i < K1 * 64; i += 256) ws[i] = enc1_w[i];
    if (tid < 81) { w1s[tid] = pw1[tid]; w2s[tid] = pw2[tid]; }
    __syncthreads();

    // ===== stage 1: enc1 conv (row-wise) + pool MLP + eta + 2x categorical =====
    for (int w = tid; w < TPI; w += 256) {
        int c = w / NTILE, nm = w % NTILE;
        int n = nm / NT, m = nm % NT;
        int y0 = 3 * n, x0 = 3 * m;
        const float* wc = &ws[c * 64];

        float t[9];
#pragma unroll
        for (int i = 0; i < 9; i++) t[i] = 0.f;

#pragma unroll
        for (int r = 0; r < 10; r++) {
            float xr[10];
#pragma unroll
            for (int v = 0; v < 10; v++) xr[v] = xs[(y0 + r) * 28 + x0 + v];
#pragma unroll
            for (int ty = 0; ty < 3; ty++) {
                int u = r - ty;
                if (u >= 0 && u < 8) {
#pragma unroll
                    for (int v = 0; v < 8; v++) {
                        float wv = wc[u * 8 + v];
                        // per-output order: u ascending, v ascending (bit-identical)
                        t[ty * 3 + 0] += xr[v + 0] * wv;
                        t[ty * 3 + 1] += xr[v + 1] * wv;
                        t[ty * 3 + 2] += xr[v + 2] * wv;
                    }
                }
            }
        }

        float l[9];
        pool_mlp(t, w1s, w2s, &out[OUT_ETA + (size_t)b * ETA_PER_B + (size_t)w * 9], l);

        uint32_t e0 = (uint32_t)b * (uint32_t)ETA_PER_B + (uint32_t)w * 9u;
        float best = -3.4e38f, best2 = -3.4e38f;
        float pv = 0.f;
        int z2 = 0;
#pragma unroll
        for (int tt = 0; tt < 9; tt++) {
            float sp = gumbelf(tf_bits(kp0, kp1, e0 + tt)) + l[tt];
            if (sp > best) { best = sp; pv = t[tt]; }
            float su = gumbelf(tf_bits(ku0, ku1, e0 + tt)) + l[tt];
            if (su > best2) { best2 = su; z2 = tt; }
        }
        pooled[w] = pv;
        zs[w] = (unsigned char)(((z2 / 3) << 2) | (z2 % 3));
    }
    __syncthreads();

    // ===== stage 2a: conv2 -> flat =====
    for (int r = tid; r < C2N; r += 256) {
        int k = r / 16, ij = r % 16, ii = ij / 4, jj = ij % 4;
        const float4* wk4 = (const float4*)&enc2_w[k * (K1 * 16)];
        float a = 0.f;
        for (int c = 0; c < K1; c++) {
            const float* pc = &pooled[c * NTILE + ii * NT + jj];
#pragma unroll
            for (int u = 0; u < 4; u++) {
                float4 wv = wk4[c * 4 + u];
                a += pc[u * NT + 0] * wv.x;
                a += pc[u * NT + 1] * wv.y;
                a += pc[u * NT + 2] * wv.z;
                a += pc[u * NT + 3] * wv.w;
            }
        }
        flat[r] = a;
    }
    __syncthreads();

    // ===== stage 2b: h = tanh(flat @ h_w^T + h_b) =====
    for (int r = tid; r < C2N; r += 256) {
        int k = r / 16;
        const float* wr = &h_w[r * 16];
        const float* fr = &flat[k * 16];
        float a = h_b[r];
#pragma unroll
        for (int i2 = 0; i2 < 16; i2++) a += fr[i2] * wr[i2];
        hsm[r] = tanhf(a);
    }
    __syncthreads();

    // ===== stage 2c: mean / logvar + reparam sample (s -> flat) =====
    for (int r = tid; r < C2N; r += 256) {
        int k = r / 16;
        const float* wm = &mean_w[r * 16];
        const float* wl = &lv_w[r * 16];
        const float* h0 = &hsm[k * 16];
        float m0 = mean_b[r], l0 = lv_b[r];
#pragma unroll
        for (int i2 = 0; i2 < 16; i2++) {
            float a = h0[i2];
            m0 += a * wm[i2];  l0 += a * wl[i2];
        }
        out[OUT_MEAN + (size_t)b * C2N + r] = m0;
        out[OUT_LV   + (size_t)b * C2N + r] = l0;

        uint32_t e = (uint32_t)b * (uint32_t)C2N + (uint32_t)r;
        flat[r] = m0 + expf(0.5f * l0) * normalf(tf_bits(kc0, kc1, e));
    }
    __syncthreads();

    // ===== stage 3: dec2 transposed conv (s=flat -> s2=pooled) =====
    if (tid < K1 * NT) {                 // 210 threads: (c1, y), 7 outputs each
        int c1 = tid / NT, y = tid % NT;
        int ilo = max(0, y - 3), ihi = min(3, y);
        float acc[7];
#pragma unroll
        for (int i = 0; i < 7; i++) acc[i] = 0.f;
        for (int c2 = 0; c2 < K2; c2++) {
            const float4* s4 = (const float4*)&flat[c2 * 16];
            const float4* w4 = (const float4*)&dec2_w[(c2 * K1 + c1) * 16];
            for (int i = ilo; i <= ihi; i++) {
                float4 sv4 = s4[i];
                float4 wv4 = w4[y - i];
                float sv[4] = {sv4.x, sv4.y, sv4.z, sv4.w};
                float wv[4] = {wv4.x, wv4.y, wv4.z, wv4.w};
#pragma unroll
                for (int j = 0; j < 4; j++)
#pragma unroll
                    for (int v = 0; v < 4; v++)
                        acc[j + v] += sv[j] * wv[v];
            }
        }
#pragma unroll
        for (int xx = 0; xx < 7; xx++)
            pooled[c1 * NTILE + y * NT + xx] = acc[xx];
    }
    __syncthreads();

    // reload ws with dec1_w
    for (int i = tid; i < K1 * 64; i += 256) ws[i] = dec1_w[i];
    __syncthreads();

    // ===== stage 4: unpool + dec1 transposed conv + diag noise =====
    float inv_alpha = 1.0f / alpha_p[0];
    for (int p = tid; p < 784; p += 256) {
        int y = p / 28, xx = p % 28;
        int nlo = (y  >= 9) ? (y  - 7) / 3 : 0;
        int nhi = min(6, y / 3);
        int mlo = (xx >= 9) ? (xx - 7) / 3 : 0;
        int mhi = min(6, xx / 3);
        float a = 0.f;
        for (int c = 0; c < K1; c++) {
            int cb = c * NTILE;
            const float* wc = &ws[c * 64];
            for (int n = nlo; n <= nhi; n++) {
                int i3 = 3 * n;
                for (int m = mlo; m <= mhi; m++) {
                    int idx = cb + n * NT + m;
                    int zv = (int)zs[idx];
                    int u = y - i3 - (zv >> 2);
                    int v = xx - 3 * m - (zv & 3);
                    if ((unsigned)u < 8u && (unsigned)v < 8u)
                        a += pooled[idx] * wc[u * 8 + v];
                }
            }
        }
        if (y == xx) {
            uint32_t e = (uint32_t)b * 784u + (uint32_t)y * 29u;
            a += inv_alpha * normalf(tf_bits(kn0, kn1, e));
        }
        out[OUT_XREC + (size_t)b * 784 + p] = a;
    }
}

// ---------------- launch ----------------
extern "C" void kernel_launch(void* const* d_in, const int* in_sizes, int n_in,
                              void* d_out, int out_size) {
    (void)in_sizes; (void)n_in; (void)out_size;
    const float* x      = (const float*)d_in[0];
    const float* enc1_w = (const float*)d_in[1];
    const float* pw1    = (const float*)d_in[2];
    const float* pw2    = (const float*)d_in[3];
    const float* enc2_w = (const float*)d_in[4];
    const float* h_w    = (const float*)d_in[5];
    const float* h_b    = (const float*)d_in[6];
    const float* mean_w = (const float*)d_in[7];
    const float* mean_b = (const float*)d_in[8];
    const float* lv_w   = (const float*)d_in[9];
    const float* lv_b   = (const float*)d_in[10];
    const float* dec2_w = (const float*)d_in[11];
    const float* dec1_w = (const float*)d_in[12];
    const float* alpha  = (const float*)d_in[13];
    float* out = (float*)d_out;

    // jax.random.key(42) = (0,42); partitionable split: key_j = tf(key, (0, j)).
    uint32_t kp0, kp1, ku0, ku1, kc0, kc1, kn0, kn1;
    tf2x32(0u, 42u, 0u, 0u, kp0, kp1);   // k_pool
    tf2x32(0u, 42u, 0u, 1u, ku0, ku1);   // k_unpool
    tf2x32(0u, 42u, 0u, 2u, kc0, kc1);   // k_code
    tf2x32(0u, 42u, 0u, 3u, kn0, kn1);   // k_noise

    k_fused<<<B_TOT, 256>>>(x, enc1_w, pw1, pw2, enc2_w, h_w, h_b,
                            mean_w, mean_b, lv_w, lv_b, dec2_w, dec1_w, alpha,
                            out, kp0, kp1, ku0, ku1, kc0, kc1, kn0, kn1);
}